// round 7
// baseline (speedup 1.0000x reference)
#include <cuda_runtime.h>
#include <math.h>

#define N_OBJ  16384
#define N_PAIR 131072
#define DD     256

// ---------------- scratch (static device memory; no allocations) ----------------
__device__ float g_objA[(size_t)N_OBJ  * DD];   // x_obj after step 0
__device__ float g_predA[(size_t)N_PAIR * DD];  // x_pred after step 0
__device__ float g_msgO[(size_t)N_OBJ  * DD];   // segment-sum target
__device__ float g_msgP[(size_t)N_PAIR * DD];   // m_s2p + m_o2p
__device__ float g_aO1[N_OBJ];   // relu(x_obj) . w_e2v[:D]
__device__ float g_aO2[N_OBJ];   // relu(x_obj) . w_v2e[D:]
__device__ float g_pP1[N_PAIR];  // relu(x_pred) . w_e2v[D:]
__device__ float g_pP2[N_PAIR];  // relu(x_pred) . w_v2e[:D]

__device__ __forceinline__ float sigf(float x) { return 1.0f / (1.0f + expf(-x)); }

// ---------------- per-row gate scalars: dot(relu(row), wA), dot(relu(row), wB) ----
__global__ void row_scalars(const float* __restrict__ X, int M,
                            const float* __restrict__ wA, const float* __restrict__ wB,
                            float* __restrict__ outA, float* __restrict__ outB)
{
    int warp = (blockIdx.x * blockDim.x + threadIdx.x) >> 5;
    int lane = threadIdx.x & 31;
    if (warp >= M) return;
    const float4* xr = (const float4*)(X + (size_t)warp * DD);
    const float4* wa4 = (const float4*)wA;
    const float4* wb4 = (const float4*)wB;
    float sA = 0.f, sB = 0.f;
#pragma unroll
    for (int h = 0; h < 2; ++h) {
        int c4 = lane + h * 32;              // 0..63 float4 chunks = 256 floats
        float4 v = xr[c4];
        float4 a = wa4[c4];
        float4 b = wb4[c4];
        float rx = fmaxf(v.x, 0.f), ry = fmaxf(v.y, 0.f);
        float rz = fmaxf(v.z, 0.f), rw = fmaxf(v.w, 0.f);
        sA += rx * a.x + ry * a.y + rz * a.z + rw * a.w;
        sB += rx * b.x + ry * b.y + rz * b.z + rw * b.w;
    }
#pragma unroll
    for (int o = 16; o > 0; o >>= 1) {
        sA += __shfl_xor_sync(0xFFFFFFFFu, sA, o);
        sB += __shfl_xor_sync(0xFFFFFFFFu, sB, o);
    }
    if (lane == 0) { outA[warp] = sA; outB[warp] = sB; }
}

// ---------------- zero msgO ----------------
__global__ void zero_kernel(float4* __restrict__ p, int n4)
{
    int i = blockIdx.x * blockDim.x + threadIdx.x;
    if (i < n4) p[i] = make_float4(0.f, 0.f, 0.f, 0.f);
}

// ---------------- edge kernel: scatter msgO (atomic), build msgP ----------------
__global__ void edge_kernel(const float* __restrict__ xp,   // x_pred  [N_PAIR][D]
                            const float* __restrict__ xo,   // x_obj   [N_OBJ][D]
                            const int*   __restrict__ pidx, // [N_PAIR][2]
                            const float* __restrict__ aO1, const float* __restrict__ aO2,
                            const float* __restrict__ pP1, const float* __restrict__ pP2,
                            const float* __restrict__ b_e2v, const float* __restrict__ b_v2e,
                            float* __restrict__ msgO, float* __restrict__ msgP)
{
    int e = (blockIdx.x * blockDim.x + threadIdx.x) >> 5;
    int lane = threadIdx.x & 31;
    if (e >= N_PAIR) return;

    int s = pidx[2 * e];
    int o = pidx[2 * e + 1];
    float be = b_e2v[0];
    float bv = b_v2e[0];
    float p1 = pP1[e], p2 = pP2[e];
    float g1 = sigf(aO1[s] + p1 + be);   // m_subj = g1 * x_pred[e]  -> msgO[s]
    float g2 = sigf(aO1[o] + p1 + be);   // m_obj  = g2 * x_pred[e]  -> msgO[o]
    float gs = sigf(aO2[s] + p2 + bv);   // m_s2p  = gs * x_obj[s]
    float go = sigf(aO2[o] + p2 + bv);   // m_o2p  = go * x_obj[o]

    const float4* xpr = (const float4*)(xp + (size_t)e * DD);
    const float4* xsr = (const float4*)(xo + (size_t)s * DD);
    const float4* xor4 = (const float4*)(xo + (size_t)o * DD);
    float4* mp  = (float4*)(msgP + (size_t)e * DD);
    float4* mos = (float4*)(msgO + (size_t)s * DD);
    float4* moo = (float4*)(msgO + (size_t)o * DD);

#pragma unroll
    for (int h = 0; h < 2; ++h) {
        int c = lane + h * 32;
        float4 vp = xpr[c];
        float4 vs = xsr[c];
        float4 vo = xor4[c];

        float4 outp;
        outp.x = gs * vs.x + go * vo.x;
        outp.y = gs * vs.y + go * vo.y;
        outp.z = gs * vs.z + go * vo.z;
        outp.w = gs * vs.w + go * vo.w;
        mp[c] = outp;

        float4 as = make_float4(g1 * vp.x, g1 * vp.y, g1 * vp.z, g1 * vp.w);
        float4 ao = make_float4(g2 * vp.x, g2 * vp.y, g2 * vp.z, g2 * vp.w);
        atomicAdd(&mos[c], as);   // vectorized float4 red (sm_90+), L2-resident target
        atomicAdd(&moo[c], ao);
    }
}

// ---------------- fused 6-way GEMM + GRU elementwise ----------------
// Y = GRU(X, H): gi = X @ Wih^T + bih ; gh = H @ Whh^T + bhh ; standard GRU cell.
// Block tile: BM=64 rows, BN=32 output cols, BK=32. 6 accumulator tiles
// (3 gates x {ih, hh}). 256 threads; each thread owns 4(m) x 2(n) x 6 accums.
#define BM 64
#define BN 32
#define BK 32

__global__ __launch_bounds__(256, 2)
void gru_kernel(const float* __restrict__ X, const float* __restrict__ H,
                const float* __restrict__ Wih, const float* __restrict__ Whh,
                const float* __restrict__ bih, const float* __restrict__ bhh,
                float* __restrict__ Y, int M)
{
    __shared__ __align__(16) float AsX[BK][BM + 4];
    __shared__ __align__(16) float AsH[BK][BM + 4];
    __shared__ __align__(16) float Bs[6][BK][BN + 2];

    const int bn = blockIdx.x;           // output-col block (0..7), d0 = bn*32
    const int bm = blockIdx.y;           // row block
    const int m0 = bm * BM;
    const int d0 = bn * BN;
    const int tid = threadIdx.x;
    const int tm = tid & 15;             // micro-tile m group (4 rows)
    const int tn = tid >> 4;             // micro-tile n group (2 cols)

    float accX[3][4][2] = {};
    float accH[3][4][2] = {};
    float hval[4][2];

    const int arow = tid >> 3;           // 0..31
    const int ac4  = tid & 7;            // 0..7 float4 chunk within BK

#pragma unroll 1
    for (int kc = 0; kc < DD / BK; ++kc) {
        const int k0 = kc * BK;
        // -------- stage A tiles (X and H), transposed to [k][m] --------
#pragma unroll
        for (int rr = 0; rr < 2; ++rr) {
            int r = arow + rr * 32;
            float4 vx = *(const float4*)(X + (size_t)(m0 + r) * DD + k0 + ac4 * 4);
            float4 vh = *(const float4*)(H + (size_t)(m0 + r) * DD + k0 + ac4 * 4);
            AsX[ac4 * 4 + 0][r] = vx.x; AsX[ac4 * 4 + 1][r] = vx.y;
            AsX[ac4 * 4 + 2][r] = vx.z; AsX[ac4 * 4 + 3][r] = vx.w;
            AsH[ac4 * 4 + 0][r] = vh.x; AsH[ac4 * 4 + 1][r] = vh.y;
            AsH[ac4 * 4 + 2][r] = vh.z; AsH[ac4 * 4 + 3][r] = vh.w;
        }
        // -------- stage 6 B tiles, transposed to [k][n] --------
#pragma unroll
        for (int g = 0; g < 6; ++g) {
            const float* W = (g < 3) ? Wih : Whh;
            int grow = (g % 3) * DD + d0 + arow;       // weight row (output col)
            float4 v = *(const float4*)(W + (size_t)grow * DD + k0 + ac4 * 4);
            Bs[g][ac4 * 4 + 0][arow] = v.x; Bs[g][ac4 * 4 + 1][arow] = v.y;
            Bs[g][ac4 * 4 + 2][arow] = v.z; Bs[g][ac4 * 4 + 3][arow] = v.w;
        }
        __syncthreads();

        if (kc == bn) {
            // H[m][d] for the z*h blend: d-cols of this block == k-cols of chunk bn
#pragma unroll
            for (int i = 0; i < 4; ++i)
#pragma unroll
                for (int j = 0; j < 2; ++j)
                    hval[i][j] = AsH[tn * 2 + j][tm * 4 + i];
        }

#pragma unroll
        for (int kk = 0; kk < BK; ++kk) {
            float4 ax = *(const float4*)&AsX[kk][tm * 4];
            float4 ah = *(const float4*)&AsH[kk][tm * 4];
            float2 b[6];
#pragma unroll
            for (int g = 0; g < 6; ++g)
                b[g] = *(const float2*)&Bs[g][kk][tn * 2];
            float am[4] = {ax.x, ax.y, ax.z, ax.w};
            float hm[4] = {ah.x, ah.y, ah.z, ah.w};
#pragma unroll
            for (int g = 0; g < 3; ++g)
#pragma unroll
                for (int i = 0; i < 4; ++i) {
                    accX[g][i][0] += am[i] * b[g].x;
                    accX[g][i][1] += am[i] * b[g].y;
                    accH[g][i][0] += hm[i] * b[g + 3].x;
                    accH[g][i][1] += hm[i] * b[g + 3].y;
                }
        }
        __syncthreads();
    }

    // -------- epilogue: GRU elementwise --------
#pragma unroll
    for (int i = 0; i < 4; ++i) {
        int m = m0 + tm * 4 + i;
        float ov[2];
#pragma unroll
        for (int j = 0; j < 2; ++j) {
            int d = d0 + tn * 2 + j;
            float ir = accX[0][i][j] + bih[d];
            float iz = accX[1][i][j] + bih[DD + d];
            float in_ = accX[2][i][j] + bih[2 * DD + d];
            float hr = accH[0][i][j] + bhh[d];
            float hz = accH[1][i][j] + bhh[DD + d];
            float hn = accH[2][i][j] + bhh[2 * DD + d];
            float r = sigf(ir + hr);
            float z = sigf(iz + hz);
            float n = tanhf(in_ + r * hn);
            ov[j] = (1.0f - z) * n + z * hval[i][j];
        }
        float2 o2 = make_float2(ov[0], ov[1]);
        *(float2*)(Y + (size_t)m * DD + d0 + tn * 2) = o2;
    }
}

// ---------------- driver ----------------
static void run_step(const float* cur_obj, const float* cur_pred,
                     float* next_obj, float* next_pred,
                     const int* pidx,
                     const float* w_e2v, const float* b_e2v,
                     const float* w_v2e, const float* b_v2e,
                     const float* w_ih, const float* w_hh,
                     const float* b_ih, const float* b_hh,
                     float* aO1, float* aO2, float* pP1, float* pP2,
                     float* msgO, float* msgP)
{
    // node gate scalars: aO1 = relu(x_obj).w_e2v[:D], aO2 = relu(x_obj).w_v2e[D:]
    row_scalars<<<(N_OBJ * 32 + 255) / 256, 256>>>(cur_obj, N_OBJ, w_e2v, w_v2e + DD, aO1, aO2);
    // edge gate scalars: pP1 = relu(x_pred).w_e2v[D:], pP2 = relu(x_pred).w_v2e[:D]
    row_scalars<<<(N_PAIR * 32 + 255) / 256, 256>>>(cur_pred, N_PAIR, w_e2v + DD, w_v2e, pP1, pP2);
    // clear segment-sum target
    zero_kernel<<<(N_OBJ * DD / 4 + 255) / 256, 256>>>((float4*)msgO, N_OBJ * DD / 4);
    // gates + scatter + pred message build
    edge_kernel<<<(N_PAIR * 32 + 255) / 256, 256>>>(cur_pred, cur_obj, pidx,
                                                    aO1, aO2, pP1, pP2,
                                                    b_e2v, b_v2e, msgO, msgP);
    // GRU updates
    gru_kernel<<<dim3(DD / BN, N_OBJ / BM), 256>>>(msgO, cur_obj, w_ih, w_hh, b_ih, b_hh,
                                                   next_obj, N_OBJ);
    gru_kernel<<<dim3(DD / BN, N_PAIR / BM), 256>>>(msgP, cur_pred, w_ih, w_hh, b_ih, b_hh,
                                                    next_pred, N_PAIR);
}

extern "C" void kernel_launch(void* const* d_in, const int* in_sizes, int n_in,
                              void* d_out, int out_size)
{
    (void)in_sizes; (void)n_in; (void)out_size;
    const float* x_obj  = (const float*)d_in[0];
    const float* x_pred = (const float*)d_in[1];
    const int*   pidx   = (const int*)d_in[2];
    const float* w_e2v  = (const float*)d_in[3];
    const float* b_e2v  = (const float*)d_in[4];
    const float* w_v2e  = (const float*)d_in[5];
    const float* b_v2e  = (const float*)d_in[6];
    const float* w_ih   = (const float*)d_in[7];
    const float* w_hh   = (const float*)d_in[8];
    const float* b_ih   = (const float*)d_in[9];
    const float* b_hh   = (const float*)d_in[10];
    float* out = (float*)d_out;

    float *objA, *predA, *msgO, *msgP, *aO1, *aO2, *pP1, *pP2;
    cudaGetSymbolAddress((void**)&objA,  g_objA);
    cudaGetSymbolAddress((void**)&predA, g_predA);
    cudaGetSymbolAddress((void**)&msgO,  g_msgO);
    cudaGetSymbolAddress((void**)&msgP,  g_msgP);
    cudaGetSymbolAddress((void**)&aO1,   g_aO1);
    cudaGetSymbolAddress((void**)&aO2,   g_aO2);
    cudaGetSymbolAddress((void**)&pP1,   g_pP1);
    cudaGetSymbolAddress((void**)&pP2,   g_pP2);

    float* out_obj  = out;
    float* out_pred = out + (size_t)N_OBJ * DD;

    // step 0: inputs -> scratch
    run_step(x_obj, x_pred, objA, predA, pidx,
             w_e2v, b_e2v, w_v2e, b_v2e, w_ih, w_hh, b_ih, b_hh,
             aO1, aO2, pP1, pP2, msgO, msgP);
    // step 1: scratch -> output
    run_step(objA, predA, out_obj, out_pred, pidx,
             w_e2v, b_e2v, w_v2e, b_v2e, w_ih, w_hh, b_ih, b_hh,
             aO1, aO2, pP1, pP2, msgO, msgP);
}

// round 8
// speedup vs baseline: 3.0759x; 3.0759x over previous
#include <cuda_runtime.h>
#include <math.h>
#include <stdint.h>

#define N_OBJ  16384
#define N_PAIR 131072
#define DD     256

// ---------------- scratch (static device memory; no allocations) ----------------
__device__ float g_objA[(size_t)N_OBJ  * DD];
__device__ float g_predA[(size_t)N_PAIR * DD];
__device__ float g_msgO[(size_t)N_OBJ  * DD];
__device__ float g_msgP[(size_t)N_PAIR * DD];
__device__ float g_aO1[N_OBJ];
__device__ float g_aO2[N_OBJ];
__device__ float g_pP1[N_PAIR];
__device__ float g_pP2[N_PAIR];

__device__ __forceinline__ float sigf(float x) { return 1.0f / (1.0f + expf(-x)); }

// ---------------- per-row gate scalars ----------------
__global__ void row_scalars(const float* __restrict__ X, int M,
                            const float* __restrict__ wA, const float* __restrict__ wB,
                            float* __restrict__ outA, float* __restrict__ outB)
{
    int warp = (blockIdx.x * blockDim.x + threadIdx.x) >> 5;
    int lane = threadIdx.x & 31;
    if (warp >= M) return;
    const float4* xr = (const float4*)(X + (size_t)warp * DD);
    const float4* wa4 = (const float4*)wA;
    const float4* wb4 = (const float4*)wB;
    float sA = 0.f, sB = 0.f;
#pragma unroll
    for (int h = 0; h < 2; ++h) {
        int c4 = lane + h * 32;
        float4 v = xr[c4];
        float4 a = wa4[c4];
        float4 b = wb4[c4];
        float rx = fmaxf(v.x, 0.f), ry = fmaxf(v.y, 0.f);
        float rz = fmaxf(v.z, 0.f), rw = fmaxf(v.w, 0.f);
        sA += rx * a.x + ry * a.y + rz * a.z + rw * a.w;
        sB += rx * b.x + ry * b.y + rz * b.z + rw * b.w;
    }
#pragma unroll
    for (int o = 16; o > 0; o >>= 1) {
        sA += __shfl_xor_sync(0xFFFFFFFFu, sA, o);
        sB += __shfl_xor_sync(0xFFFFFFFFu, sB, o);
    }
    if (lane == 0) { outA[warp] = sA; outB[warp] = sB; }
}

// ---------------- zero msgO ----------------
__global__ void zero_kernel(float4* __restrict__ p, int n4)
{
    int i = blockIdx.x * blockDim.x + threadIdx.x;
    if (i < n4) p[i] = make_float4(0.f, 0.f, 0.f, 0.f);
}

// ---------------- edge kernel ----------------
__global__ void edge_kernel(const float* __restrict__ xp,
                            const float* __restrict__ xo,
                            const int*   __restrict__ pidx,
                            const float* __restrict__ aO1, const float* __restrict__ aO2,
                            const float* __restrict__ pP1, const float* __restrict__ pP2,
                            const float* __restrict__ b_e2v, const float* __restrict__ b_v2e,
                            float* __restrict__ msgO, float* __restrict__ msgP)
{
    int e = (blockIdx.x * blockDim.x + threadIdx.x) >> 5;
    int lane = threadIdx.x & 31;
    if (e >= N_PAIR) return;

    int s = pidx[2 * e];
    int o = pidx[2 * e + 1];
    float be = b_e2v[0];
    float bv = b_v2e[0];
    float p1 = pP1[e], p2 = pP2[e];
    float g1 = sigf(aO1[s] + p1 + be);
    float g2 = sigf(aO1[o] + p1 + be);
    float gs = sigf(aO2[s] + p2 + bv);
    float go = sigf(aO2[o] + p2 + bv);

    const float4* xpr = (const float4*)(xp + (size_t)e * DD);
    const float4* xsr = (const float4*)(xo + (size_t)s * DD);
    const float4* xor4 = (const float4*)(xo + (size_t)o * DD);
    float4* mp  = (float4*)(msgP + (size_t)e * DD);
    float4* mos = (float4*)(msgO + (size_t)s * DD);
    float4* moo = (float4*)(msgO + (size_t)o * DD);

#pragma unroll
    for (int h = 0; h < 2; ++h) {
        int c = lane + h * 32;
        float4 vp = xpr[c];
        float4 vs = xsr[c];
        float4 vo = xor4[c];

        float4 outp;
        outp.x = gs * vs.x + go * vo.x;
        outp.y = gs * vs.y + go * vo.y;
        outp.z = gs * vs.z + go * vo.z;
        outp.w = gs * vs.w + go * vo.w;
        mp[c] = outp;

        float4 as = make_float4(g1 * vp.x, g1 * vp.y, g1 * vp.z, g1 * vp.w);
        float4 ao = make_float4(g2 * vp.x, g2 * vp.y, g2 * vp.z, g2 * vp.w);
        atomicAdd(&mos[c], as);
        atomicAdd(&moo[c], ao);
    }
}

// ================= tf32 tensor-core fused GRU =================
// Y = GRU(X, H). Per d-column block of 32, 4 accumulator groups:
//   accR = X@Wr_ih^T + H@Wr_hh^T   (r gate, combined K=512)
//   accZ = X@Wz_ih^T + H@Wz_hh^T
//   accI = X@Wn_ih^T               (i_n)
//   accN = H@Wn_hh^T               (h_n)
// Epilogue: r=sig(accR+br), z=sig(accZ+bz), n=tanh(accI+bi + r*(accN+bn)),
//           y = (1-z)*n + z*H.
#define TBM 128
#define TBN 32
#define TBK 16
#define ASTR 20   // padded smem row stride (floats); r*20 mod 32 banks is a permutation

#define TC_SMEM_FLOATS (2*TBM*ASTR /*AsX*/ + 2*TBM*ASTR /*AsH*/ + 2*6*32*ASTR /*Bs*/)
#define TC_SMEM_BYTES  (TC_SMEM_FLOATS * 4)

__device__ __forceinline__ uint32_t smem_u32(const void* p) {
    return (uint32_t)__cvta_generic_to_shared(p);
}
#define CP16(dst, src) \
    asm volatile("cp.async.cg.shared.global [%0], [%1], 16;\n" :: "r"(dst), "l"(src) : "memory")
__device__ __forceinline__ void cp_commit() {
    asm volatile("cp.async.commit_group;\n" ::: "memory");
}
template<int N> __device__ __forceinline__ void cp_wait() {
    asm volatile("cp.async.wait_group %0;\n" :: "n"(N) : "memory");
}
__device__ __forceinline__ void ldsm4(uint32_t* r, uint32_t addr) {
    asm volatile("ldmatrix.sync.aligned.m8n8.x4.shared.b16 {%0,%1,%2,%3}, [%4];\n"
        : "=r"(r[0]), "=r"(r[1]), "=r"(r[2]), "=r"(r[3]) : "r"(addr));
}
__device__ __forceinline__ void mma_tf32(float* c, const uint32_t* a, const uint32_t* b) {
    asm volatile("mma.sync.aligned.m16n8k8.row.col.f32.tf32.tf32.f32 "
        "{%0,%1,%2,%3}, {%4,%5,%6,%7}, {%8,%9}, {%0,%1,%2,%3};\n"
        : "+f"(c[0]), "+f"(c[1]), "+f"(c[2]), "+f"(c[3])
        : "r"(a[0]), "r"(a[1]), "r"(a[2]), "r"(a[3]), "r"(b[0]), "r"(b[1]));
}

__global__ __launch_bounds__(256, 2)
void gru_tc(const float* __restrict__ X, const float* __restrict__ H,
            const float* __restrict__ Wih, const float* __restrict__ Whh,
            const float* __restrict__ bih, const float* __restrict__ bhh,
            float* __restrict__ Y)
{
    extern __shared__ float smem[];
    float* AsX = smem;                      // [2][128][ASTR]
    float* AsH = AsX + 2 * TBM * ASTR;      // [2][128][ASTR]
    float* Bs  = AsH + 2 * TBM * ASTR;      // [2][6][32][ASTR]

    const int tid  = threadIdx.x;
    const int lane = tid & 31;
    const int w    = tid >> 5;
    const int wm   = w >> 1;     // 0..3: warp m-row (32 rows each)
    const int wn   = w & 1;      // 0..1: warp n-col (16 cols each)
    const int m0   = blockIdx.y * TBM;
    const int d0   = blockIdx.x * TBN;

    float acc[4][2][2][4] = {};  // [gate][mi][ni][reg]

    // ldmatrix per-lane address components
    const int rowA  = lane & 15;
    const int colAh = (lane & 16) ? 4 : 0;
    const int rowB  = (lane & 7) + ((lane & 16) >> 1);
    const int colBh = (lane & 8) ? 4 : 0;

    const int NSTAGE = DD / TBK;  // 16

    // ---- staging: global -> smem via cp.async ----
    auto stage = [&](int kc, int buf) {
        const int k0 = kc * TBK;
#pragma unroll
        for (int j = 0; j < 2; ++j) {
            int f = tid + 256 * j;          // 0..511
            int row = f >> 2;               // 0..127
            int k4  = (f & 3) << 2;         // 0,4,8,12
            uint32_t dx = smem_u32(AsX + buf * TBM * ASTR + row * ASTR + k4);
            CP16(dx, X + (size_t)(m0 + row) * DD + k0 + k4);
            uint32_t dh = smem_u32(AsH + buf * TBM * ASTR + row * ASTR + k4);
            CP16(dh, H + (size_t)(m0 + row) * DD + k0 + k4);
        }
#pragma unroll
        for (int j = 0; j < 3; ++j) {
            int f = tid + 256 * j;          // 0..767
            int g = f >> 7;                 // 0..5
            int r = (f >> 2) & 31;
            int k4 = (f & 3) << 2;
            const float* W = (g < 3) ? Wih : Whh;
            int grow = (g % 3) * DD + d0 + r;
            uint32_t db = smem_u32(Bs + buf * 6 * 32 * ASTR + g * 32 * ASTR + r * ASTR + k4);
            CP16(db, W + (size_t)grow * DD + k0 + k4);
        }
    };

    stage(0, 0);
    cp_commit();

#pragma unroll 1
    for (int kc = 0; kc < NSTAGE; ++kc) {
        const int buf = kc & 1;
        if (kc + 1 < NSTAGE) {
            stage(kc + 1, buf ^ 1);
            cp_commit();
            cp_wait<1>();
        } else {
            cp_wait<0>();
        }
        __syncthreads();

        const float* aXb = AsX + buf * TBM * ASTR;
        const float* aHb = AsH + buf * TBM * ASTR;
        const float* bb  = Bs  + buf * 6 * 32 * ASTR;

#pragma unroll
        for (int c = 0; c < 2; ++c) {       // two k8 chunks per stage
            uint32_t aX[2][4], aH[2][4], bf[6][4];
#pragma unroll
            for (int mi = 0; mi < 2; ++mi) {
                ldsm4(aX[mi], smem_u32(aXb + (wm * 32 + mi * 16 + rowA) * ASTR + c * 8 + colAh));
                ldsm4(aH[mi], smem_u32(aHb + (wm * 32 + mi * 16 + rowA) * ASTR + c * 8 + colAh));
            }
#pragma unroll
            for (int g = 0; g < 6; ++g) {
                ldsm4(bf[g], smem_u32(bb + g * 32 * ASTR + (wn * 16 + rowB) * ASTR + c * 8 + colBh));
            }
#pragma unroll
            for (int mi = 0; mi < 2; ++mi)
#pragma unroll
            for (int ni = 0; ni < 2; ++ni) {
                mma_tf32(acc[0][mi][ni], aX[mi], &bf[0][2 * ni]);  // r: X@Wr_ih
                mma_tf32(acc[0][mi][ni], aH[mi], &bf[3][2 * ni]);  // r: H@Wr_hh
                mma_tf32(acc[1][mi][ni], aX[mi], &bf[1][2 * ni]);  // z: X@Wz_ih
                mma_tf32(acc[1][mi][ni], aH[mi], &bf[4][2 * ni]);  // z: H@Wz_hh
                mma_tf32(acc[2][mi][ni], aX[mi], &bf[2][2 * ni]);  // i_n
                mma_tf32(acc[3][mi][ni], aH[mi], &bf[5][2 * ni]);  // h_n
            }
        }
        __syncthreads();
    }

    // ---- fused GRU epilogue ----
    const int mwarp = m0 + wm * 32;
    const int dwarp = d0 + wn * 16;
#pragma unroll
    for (int ni = 0; ni < 2; ++ni) {
        const int dA = dwarp + ni * 8 + (lane & 3) * 2;   // two consecutive cols dA, dA+1
        const float brA = __ldg(bih + dA)          + __ldg(bhh + dA);
        const float brB = __ldg(bih + dA + 1)      + __ldg(bhh + dA + 1);
        const float bzA = __ldg(bih + DD + dA)     + __ldg(bhh + DD + dA);
        const float bzB = __ldg(bih + DD + dA + 1) + __ldg(bhh + DD + dA + 1);
        const float biA = __ldg(bih + 2 * DD + dA);
        const float biB = __ldg(bih + 2 * DD + dA + 1);
        const float bnA = __ldg(bhh + 2 * DD + dA);
        const float bnB = __ldg(bhh + 2 * DD + dA + 1);
#pragma unroll
        for (int mi = 0; mi < 2; ++mi) {
#pragma unroll
            for (int p = 0; p < 2; ++p) {
                const int m = mwarp + mi * 16 + (lane >> 2) + p * 8;
                const float cr0 = acc[0][mi][ni][2 * p], cr1 = acc[0][mi][ni][2 * p + 1];
                const float cz0 = acc[1][mi][ni][2 * p], cz1 = acc[1][mi][ni][2 * p + 1];
                const float ci0 = acc[2][mi][ni][2 * p], ci1 = acc[2][mi][ni][2 * p + 1];
                const float cn0 = acc[3][mi][ni][2 * p], cn1 = acc[3][mi][ni][2 * p + 1];
                const float2 h2 = *(const float2*)(H + (size_t)m * DD + dA);
                const float r0 = sigf(cr0 + brA);
                const float r1 = sigf(cr1 + brB);
                const float z0 = sigf(cz0 + bzA);
                const float z1 = sigf(cz1 + bzB);
                const float n0 = tanhf(ci0 + biA + r0 * (cn0 + bnA));
                const float n1 = tanhf(ci1 + biB + r1 * (cn1 + bnB));
                float2 y2;
                y2.x = (1.0f - z0) * n0 + z0 * h2.x;
                y2.y = (1.0f - z1) * n1 + z1 * h2.y;
                *(float2*)(Y + (size_t)m * DD + dA) = y2;
            }
        }
    }
}

// ---------------- driver ----------------
static void run_step(const float* cur_obj, const float* cur_pred,
                     float* next_obj, float* next_pred,
                     const int* pidx,
                     const float* w_e2v, const float* b_e2v,
                     const float* w_v2e, const float* b_v2e,
                     const float* w_ih, const float* w_hh,
                     const float* b_ih, const float* b_hh,
                     float* aO1, float* aO2, float* pP1, float* pP2,
                     float* msgO, float* msgP)
{
    row_scalars<<<(N_OBJ * 32 + 255) / 256, 256>>>(cur_obj, N_OBJ, w_e2v, w_v2e + DD, aO1, aO2);
    row_scalars<<<(N_PAIR * 32 + 255) / 256, 256>>>(cur_pred, N_PAIR, w_e2v + DD, w_v2e, pP1, pP2);
    zero_kernel<<<(N_OBJ * DD / 4 + 255) / 256, 256>>>((float4*)msgO, N_OBJ * DD / 4);
    edge_kernel<<<(N_PAIR * 32 + 255) / 256, 256>>>(cur_pred, cur_obj, pidx,
                                                    aO1, aO2, pP1, pP2,
                                                    b_e2v, b_v2e, msgO, msgP);
    gru_tc<<<dim3(DD / TBN, N_OBJ / TBM), 256, TC_SMEM_BYTES>>>(
        msgO, cur_obj, w_ih, w_hh, b_ih, b_hh, next_obj);
    gru_tc<<<dim3(DD / TBN, N_PAIR / TBM), 256, TC_SMEM_BYTES>>>(
        msgP, cur_pred, w_ih, w_hh, b_ih, b_hh, next_pred);
}

extern "C" void kernel_launch(void* const* d_in, const int* in_sizes, int n_in,
                              void* d_out, int out_size)
{
    (void)in_sizes; (void)n_in; (void)out_size;
    const float* x_obj  = (const float*)d_in[0];
    const float* x_pred = (const float*)d_in[1];
    const int*   pidx   = (const int*)d_in[2];
    const float* w_e2v  = (const float*)d_in[3];
    const float* b_e2v  = (const float*)d_in[4];
    const float* w_v2e  = (const float*)d_in[5];
    const float* b_v2e  = (const float*)d_in[6];
    const float* w_ih   = (const float*)d_in[7];
    const float* w_hh   = (const float*)d_in[8];
    const float* b_ih   = (const float*)d_in[9];
    const float* b_hh   = (const float*)d_in[10];
    float* out = (float*)d_out;

    cudaFuncSetAttribute(gru_tc, cudaFuncAttributeMaxDynamicSharedMemorySize, TC_SMEM_BYTES);

    float *objA, *predA, *msgO, *msgP, *aO1, *aO2, *pP1, *pP2;
    cudaGetSymbolAddress((void**)&objA,  g_objA);
    cudaGetSymbolAddress((void**)&predA, g_predA);
    cudaGetSymbolAddress((void**)&msgO,  g_msgO);
    cudaGetSymbolAddress((void**)&msgP,  g_msgP);
    cudaGetSymbolAddress((void**)&aO1,   g_aO1);
    cudaGetSymbolAddress((void**)&aO2,   g_aO2);
    cudaGetSymbolAddress((void**)&pP1,   g_pP1);
    cudaGetSymbolAddress((void**)&pP2,   g_pP2);

    float* out_obj  = out;
    float* out_pred = out + (size_t)N_OBJ * DD;

    run_step(x_obj, x_pred, objA, predA, pidx,
             w_e2v, b_e2v, w_v2e, b_v2e, w_ih, w_hh, b_ih, b_hh,
             aO1, aO2, pP1, pP2, msgO, msgP);
    run_step(objA, predA, out_obj, out_pred, pidx,
             w_e2v, b_e2v, w_v2e, b_v2e, w_ih, w_hh, b_ih, b_hh,
             aO1, aO2, pP1, pP2, msgO, msgP);
}

// round 9
// speedup vs baseline: 3.0771x; 1.0004x over previous
#include <cuda_runtime.h>
#include <math.h>
#include <stdint.h>

#define N_OBJ  16384
#define N_PAIR 131072
#define DD     256

// ---------------- scratch (static device memory; no allocations) ----------------
__device__ float g_objA[(size_t)N_OBJ  * DD];
__device__ float g_predA[(size_t)N_PAIR * DD];
__device__ float g_msgO[(size_t)N_OBJ  * DD];
__device__ float g_msgP[(size_t)N_PAIR * DD];
__device__ float g_aO1[N_OBJ];
__device__ float g_aO2[N_OBJ];
__device__ float g_pP1[N_PAIR];
__device__ float g_pP2[N_PAIR];

__device__ __forceinline__ float sigf(float x) { return 1.0f / (1.0f + expf(-x)); }

// ---------------- per-row gate scalars ----------------
__global__ void row_scalars(const float* __restrict__ X, int M,
                            const float* __restrict__ wA, const float* __restrict__ wB,
                            float* __restrict__ outA, float* __restrict__ outB)
{
    int warp = (blockIdx.x * blockDim.x + threadIdx.x) >> 5;
    int lane = threadIdx.x & 31;
    if (warp >= M) return;
    const float4* xr = (const float4*)(X + (size_t)warp * DD);
    const float4* wa4 = (const float4*)wA;
    const float4* wb4 = (const float4*)wB;
    float sA = 0.f, sB = 0.f;
#pragma unroll
    for (int h = 0; h < 2; ++h) {
        int c4 = lane + h * 32;
        float4 v = xr[c4];
        float4 a = wa4[c4];
        float4 b = wb4[c4];
        float rx = fmaxf(v.x, 0.f), ry = fmaxf(v.y, 0.f);
        float rz = fmaxf(v.z, 0.f), rw = fmaxf(v.w, 0.f);
        sA += rx * a.x + ry * a.y + rz * a.z + rw * a.w;
        sB += rx * b.x + ry * b.y + rz * b.z + rw * b.w;
    }
#pragma unroll
    for (int o = 16; o > 0; o >>= 1) {
        sA += __shfl_xor_sync(0xFFFFFFFFu, sA, o);
        sB += __shfl_xor_sync(0xFFFFFFFFu, sB, o);
    }
    if (lane == 0) { outA[warp] = sA; outB[warp] = sB; }
}

// ---------------- zero msgO ----------------
__global__ void zero_kernel(float4* __restrict__ p, int n4)
{
    int i = blockIdx.x * blockDim.x + threadIdx.x;
    if (i < n4) p[i] = make_float4(0.f, 0.f, 0.f, 0.f);
}

// ---------------- edge kernel ----------------
__global__ void edge_kernel(const float* __restrict__ xp,
                            const float* __restrict__ xo,
                            const int*   __restrict__ pidx,
                            const float* __restrict__ aO1, const float* __restrict__ aO2,
                            const float* __restrict__ pP1, const float* __restrict__ pP2,
                            const float* __restrict__ b_e2v, const float* __restrict__ b_v2e,
                            float* __restrict__ msgO, float* __restrict__ msgP)
{
    int e = (blockIdx.x * blockDim.x + threadIdx.x) >> 5;
    int lane = threadIdx.x & 31;
    if (e >= N_PAIR) return;

    int s = pidx[2 * e];
    int o = pidx[2 * e + 1];
    float be = b_e2v[0];
    float bv = b_v2e[0];
    float p1 = pP1[e], p2 = pP2[e];
    float g1 = sigf(aO1[s] + p1 + be);
    float g2 = sigf(aO1[o] + p1 + be);
    float gs = sigf(aO2[s] + p2 + bv);
    float go = sigf(aO2[o] + p2 + bv);

    const float4* xpr = (const float4*)(xp + (size_t)e * DD);
    const float4* xsr = (const float4*)(xo + (size_t)s * DD);
    const float4* xor4 = (const float4*)(xo + (size_t)o * DD);
    float4* mp  = (float4*)(msgP + (size_t)e * DD);
    float4* mos = (float4*)(msgO + (size_t)s * DD);
    float4* moo = (float4*)(msgO + (size_t)o * DD);

#pragma unroll
    for (int h = 0; h < 2; ++h) {
        int c = lane + h * 32;
        float4 vp = xpr[c];
        float4 vs = xsr[c];
        float4 vo = xor4[c];

        float4 outp;
        outp.x = gs * vs.x + go * vo.x;
        outp.y = gs * vs.y + go * vo.y;
        outp.z = gs * vs.z + go * vo.z;
        outp.w = gs * vs.w + go * vo.w;
        mp[c] = outp;

        float4 as = make_float4(g1 * vp.x, g1 * vp.y, g1 * vp.z, g1 * vp.w);
        float4 ao = make_float4(g2 * vp.x, g2 * vp.y, g2 * vp.z, g2 * vp.w);
        atomicAdd(&mos[c], as);
        atomicAdd(&moo[c], ao);
    }
}

// ================= tf32 tensor-core fused GRU =================
// Y = GRU(X, H). Per d-column block of 32, 4 accumulator groups:
//   accR = X@Wr_ih^T + H@Wr_hh^T   (r gate, combined K=512)
//   accZ = X@Wz_ih^T + H@Wz_hh^T
//   accI = X@Wn_ih^T               (i_n)
//   accN = H@Wn_hh^T               (h_n)
// Epilogue: r=sig(accR+br), z=sig(accZ+bz), n=tanh(accI+bi + r*(accN+bn)),
//           y = (1-z)*n + z*H.
#define TBM 128
#define TBN 32
#define TBK 16
#define ASTR 20   // padded smem row stride (floats); r*20 mod 32 banks is a permutation

#define TC_SMEM_FLOATS (2*TBM*ASTR /*AsX*/ + 2*TBM*ASTR /*AsH*/ + 2*6*32*ASTR /*Bs*/)
#define TC_SMEM_BYTES  (TC_SMEM_FLOATS * 4)

__device__ __forceinline__ uint32_t smem_u32(const void* p) {
    return (uint32_t)__cvta_generic_to_shared(p);
}
#define CP16(dst, src) \
    asm volatile("cp.async.cg.shared.global [%0], [%1], 16;\n" :: "r"(dst), "l"(src) : "memory")
__device__ __forceinline__ void cp_commit() {
    asm volatile("cp.async.commit_group;\n" ::: "memory");
}
template<int N> __device__ __forceinline__ void cp_wait() {
    asm volatile("cp.async.wait_group %0;\n" :: "n"(N) : "memory");
}
__device__ __forceinline__ void ldsm4(uint32_t* r, uint32_t addr) {
    asm volatile("ldmatrix.sync.aligned.m8n8.x4.shared.b16 {%0,%1,%2,%3}, [%4];\n"
        : "=r"(r[0]), "=r"(r[1]), "=r"(r[2]), "=r"(r[3]) : "r"(addr));
}
__device__ __forceinline__ void mma_tf32(float* c, const uint32_t* a, const uint32_t* b) {
    asm volatile("mma.sync.aligned.m16n8k8.row.col.f32.tf32.tf32.f32 "
        "{%0,%1,%2,%3}, {%4,%5,%6,%7}, {%8,%9}, {%0,%1,%2,%3};\n"
        : "+f"(c[0]), "+f"(c[1]), "+f"(c[2]), "+f"(c[3])
        : "r"(a[0]), "r"(a[1]), "r"(a[2]), "r"(a[3]), "r"(b[0]), "r"(b[1]));
}

__global__ __launch_bounds__(256, 2)
void gru_tc(const float* __restrict__ X, const float* __restrict__ H,
            const float* __restrict__ Wih, const float* __restrict__ Whh,
            const float* __restrict__ bih, const float* __restrict__ bhh,
            float* __restrict__ Y)
{
    extern __shared__ float smem[];
    float* AsX = smem;                      // [2][128][ASTR]
    float* AsH = AsX + 2 * TBM * ASTR;      // [2][128][ASTR]
    float* Bs  = AsH + 2 * TBM * ASTR;      // [2][6][32][ASTR]

    const int tid  = threadIdx.x;
    const int lane = tid & 31;
    const int w    = tid >> 5;
    const int wm   = w >> 1;     // 0..3: warp m-row (32 rows each)
    const int wn   = w & 1;      // 0..1: warp n-col (16 cols each)
    const int m0   = blockIdx.y * TBM;
    const int d0   = blockIdx.x * TBN;

    float acc[4][2][2][4] = {};  // [gate][mi][ni][reg]

    // ldmatrix per-lane address components
    const int rowA  = lane & 15;
    const int colAh = (lane & 16) ? 4 : 0;
    const int rowB  = (lane & 7) + ((lane & 16) >> 1);
    const int colBh = (lane & 8) ? 4 : 0;

    const int NSTAGE = DD / TBK;  // 16

    // ---- staging: global -> smem via cp.async ----
    auto stage = [&](int kc, int buf) {
        const int k0 = kc * TBK;
#pragma unroll
        for (int j = 0; j < 2; ++j) {
            int f = tid + 256 * j;          // 0..511
            int row = f >> 2;               // 0..127
            int k4  = (f & 3) << 2;         // 0,4,8,12
            uint32_t dx = smem_u32(AsX + buf * TBM * ASTR + row * ASTR + k4);
            CP16(dx, X + (size_t)(m0 + row) * DD + k0 + k4);
            uint32_t dh = smem_u32(AsH + buf * TBM * ASTR + row * ASTR + k4);
            CP16(dh, H + (size_t)(m0 + row) * DD + k0 + k4);
        }
#pragma unroll
        for (int j = 0; j < 3; ++j) {
            int f = tid + 256 * j;          // 0..767
            int g = f >> 7;                 // 0..5
            int r = (f >> 2) & 31;
            int k4 = (f & 3) << 2;
            const float* W = (g < 3) ? Wih : Whh;
            int grow = (g % 3) * DD + d0 + r;
            uint32_t db = smem_u32(Bs + buf * 6 * 32 * ASTR + g * 32 * ASTR + r * ASTR + k4);
            CP16(db, W + (size_t)grow * DD + k0 + k4);
        }
    };

    stage(0, 0);
    cp_commit();

#pragma unroll 1
    for (int kc = 0; kc < NSTAGE; ++kc) {
        const int buf = kc & 1;
        if (kc + 1 < NSTAGE) {
            stage(kc + 1, buf ^ 1);
            cp_commit();
            cp_wait<1>();
        } else {
            cp_wait<0>();
        }
        __syncthreads();

        const float* aXb = AsX + buf * TBM * ASTR;
        const float* aHb = AsH + buf * TBM * ASTR;
        const float* bb  = Bs  + buf * 6 * 32 * ASTR;

#pragma unroll
        for (int c = 0; c < 2; ++c) {       // two k8 chunks per stage
            uint32_t aX[2][4], aH[2][4], bf[6][4];
#pragma unroll
            for (int mi = 0; mi < 2; ++mi) {
                ldsm4(aX[mi], smem_u32(aXb + (wm * 32 + mi * 16 + rowA) * ASTR + c * 8 + colAh));
                ldsm4(aH[mi], smem_u32(aHb + (wm * 32 + mi * 16 + rowA) * ASTR + c * 8 + colAh));
            }
#pragma unroll
            for (int g = 0; g < 6; ++g) {
                ldsm4(bf[g], smem_u32(bb + g * 32 * ASTR + (wn * 16 + rowB) * ASTR + c * 8 + colBh));
            }
#pragma unroll
            for (int mi = 0; mi < 2; ++mi)
#pragma unroll
            for (int ni = 0; ni < 2; ++ni) {
                mma_tf32(acc[0][mi][ni], aX[mi], &bf[0][2 * ni]);  // r: X@Wr_ih
                mma_tf32(acc[0][mi][ni], aH[mi], &bf[3][2 * ni]);  // r: H@Wr_hh
                mma_tf32(acc[1][mi][ni], aX[mi], &bf[1][2 * ni]);  // z: X@Wz_ih
                mma_tf32(acc[1][mi][ni], aH[mi], &bf[4][2 * ni]);  // z: H@Wz_hh
                mma_tf32(acc[2][mi][ni], aX[mi], &bf[2][2 * ni]);  // i_n
                mma_tf32(acc[3][mi][ni], aH[mi], &bf[5][2 * ni]);  // h_n
            }
        }
        __syncthreads();
    }

    // ---- fused GRU epilogue ----
    const int mwarp = m0 + wm * 32;
    const int dwarp = d0 + wn * 16;
#pragma unroll
    for (int ni = 0; ni < 2; ++ni) {
        const int dA = dwarp + ni * 8 + (lane & 3) * 2;   // two consecutive cols dA, dA+1
        const float brA = __ldg(bih + dA)          + __ldg(bhh + dA);
        const float brB = __ldg(bih + dA + 1)      + __ldg(bhh + dA + 1);
        const float bzA = __ldg(bih + DD + dA)     + __ldg(bhh + DD + dA);
        const float bzB = __ldg(bih + DD + dA + 1) + __ldg(bhh + DD + dA + 1);
        const float biA = __ldg(bih + 2 * DD + dA);
        const float biB = __ldg(bih + 2 * DD + dA + 1);
        const float bnA = __ldg(bhh + 2 * DD + dA);
        const float bnB = __ldg(bhh + 2 * DD + dA + 1);
#pragma unroll
        for (int mi = 0; mi < 2; ++mi) {
#pragma unroll
            for (int p = 0; p < 2; ++p) {
                const int m = mwarp + mi * 16 + (lane >> 2) + p * 8;
                const float cr0 = acc[0][mi][ni][2 * p], cr1 = acc[0][mi][ni][2 * p + 1];
                const float cz0 = acc[1][mi][ni][2 * p], cz1 = acc[1][mi][ni][2 * p + 1];
                const float ci0 = acc[2][mi][ni][2 * p], ci1 = acc[2][mi][ni][2 * p + 1];
                const float cn0 = acc[3][mi][ni][2 * p], cn1 = acc[3][mi][ni][2 * p + 1];
                const float2 h2 = *(const float2*)(H + (size_t)m * DD + dA);
                const float r0 = sigf(cr0 + brA);
                const float r1 = sigf(cr1 + brB);
                const float z0 = sigf(cz0 + bzA);
                const float z1 = sigf(cz1 + bzB);
                const float n0 = tanhf(ci0 + biA + r0 * (cn0 + bnA));
                const float n1 = tanhf(ci1 + biB + r1 * (cn1 + bnB));
                float2 y2;
                y2.x = (1.0f - z0) * n0 + z0 * h2.x;
                y2.y = (1.0f - z1) * n1 + z1 * h2.y;
                *(float2*)(Y + (size_t)m * DD + dA) = y2;
            }
        }
    }
}

// ---------------- driver ----------------
static void run_step(const float* cur_obj, const float* cur_pred,
                     float* next_obj, float* next_pred,
                     const int* pidx,
                     const float* w_e2v, const float* b_e2v,
                     const float* w_v2e, const float* b_v2e,
                     const float* w_ih, const float* w_hh,
                     const float* b_ih, const float* b_hh,
                     float* aO1, float* aO2, float* pP1, float* pP2,
                     float* msgO, float* msgP)
{
    row_scalars<<<(N_OBJ * 32 + 255) / 256, 256>>>(cur_obj, N_OBJ, w_e2v, w_v2e + DD, aO1, aO2);
    row_scalars<<<(N_PAIR * 32 + 255) / 256, 256>>>(cur_pred, N_PAIR, w_e2v + DD, w_v2e, pP1, pP2);
    zero_kernel<<<(N_OBJ * DD / 4 + 255) / 256, 256>>>((float4*)msgO, N_OBJ * DD / 4);
    edge_kernel<<<(N_PAIR * 32 + 255) / 256, 256>>>(cur_pred, cur_obj, pidx,
                                                    aO1, aO2, pP1, pP2,
                                                    b_e2v, b_v2e, msgO, msgP);
    gru_tc<<<dim3(DD / TBN, N_OBJ / TBM), 256, TC_SMEM_BYTES>>>(
        msgO, cur_obj, w_ih, w_hh, b_ih, b_hh, next_obj);
    gru_tc<<<dim3(DD / TBN, N_PAIR / TBM), 256, TC_SMEM_BYTES>>>(
        msgP, cur_pred, w_ih, w_hh, b_ih, b_hh, next_pred);
}

extern "C" void kernel_launch(void* const* d_in, const int* in_sizes, int n_in,
                              void* d_out, int out_size)
{
    (void)in_sizes; (void)n_in; (void)out_size;
    const float* x_obj  = (const float*)d_in[0];
    const float* x_pred = (const float*)d_in[1];
    const int*   pidx   = (const int*)d_in[2];
    const float* w_e2v  = (const float*)d_in[3];
    const float* b_e2v  = (const float*)d_in[4];
    const float* w_v2e  = (const float*)d_in[5];
    const float* b_v2e  = (const float*)d_in[6];
    const float* w_ih   = (const float*)d_in[7];
    const float* w_hh   = (const float*)d_in[8];
    const float* b_ih   = (const float*)d_in[9];
    const float* b_hh   = (const float*)d_in[10];
    float* out = (float*)d_out;

    cudaFuncSetAttribute(gru_tc, cudaFuncAttributeMaxDynamicSharedMemorySize, TC_SMEM_BYTES);

    float *objA, *predA, *msgO, *msgP, *aO1, *aO2, *pP1, *pP2;
    cudaGetSymbolAddress((void**)&objA,  g_objA);
    cudaGetSymbolAddress((void**)&predA, g_predA);
    cudaGetSymbolAddress((void**)&msgO,  g_msgO);
    cudaGetSymbolAddress((void**)&msgP,  g_msgP);
    cudaGetSymbolAddress((void**)&aO1,   g_aO1);
    cudaGetSymbolAddress((void**)&aO2,   g_aO2);
    cudaGetSymbolAddress((void**)&pP1,   g_pP1);
    cudaGetSymbolAddress((void**)&pP2,   g_pP2);

    float* out_obj  = out;
    float* out_pred = out + (size_t)N_OBJ * DD;

    run_step(x_obj, x_pred, objA, predA, pidx,
             w_e2v, b_e2v, w_v2e, b_v2e, w_ih, w_hh, b_ih, b_hh,
             aO1, aO2, pP1, pP2, msgO, msgP);
    run_step(objA, predA, out_obj, out_pred, pidx,
             w_e2v, b_e2v, w_v2e, b_v2e, w_ih, w_hh, b_ih, b_hh,
             aO1, aO2, pP1, pP2, msgO, msgP);
}

// round 11
// speedup vs baseline: 4.5137x; 1.4669x over previous
#include <cuda_runtime.h>
#include <cuda_fp16.h>
#include <math.h>
#include <stdint.h>

#define N_OBJ  16384
#define N_PAIR 131072
#define DD     256

// ---------------- scratch (static device memory; no allocations) ----------------
__device__ float g_objA[(size_t)N_OBJ  * DD];
__device__ float g_predA[(size_t)N_PAIR * DD];
__device__ float g_msgO[(size_t)N_OBJ  * DD];
__device__ float g_aO1[N_OBJ];
__device__ float g_aO2[N_OBJ];
__device__ float g_pP1[N_PAIR];
__device__ float g_pP2[N_PAIR];
// half-precision MMA operand buffers
__device__ __half g_msgP_h[(size_t)N_PAIR * DD];
__device__ __half g_msgO_h[(size_t)N_OBJ  * DD];
__device__ __half g_objH_h[(size_t)N_OBJ  * DD];
__device__ __half g_predH_h[(size_t)N_PAIR * DD];
__device__ __half g_Wih_h[3 * DD * DD];
__device__ __half g_Whh_h[3 * DD * DD];

__device__ __forceinline__ float sigf(float x) { return 1.0f / (1.0f + expf(-x)); }

// ---------------- float -> half conversion (8 elems / thread) ----------------
__global__ void f2h_kernel(const float* __restrict__ src, __half* __restrict__ dst, int n8)
{
    int i = blockIdx.x * blockDim.x + threadIdx.x;
    if (i >= n8) return;
    const float4* s4 = (const float4*)src;
    float4 a = s4[2 * i];
    float4 b = s4[2 * i + 1];
    __half2 h[4];
    h[0] = __floats2half2_rn(a.x, a.y);
    h[1] = __floats2half2_rn(a.z, a.w);
    h[2] = __floats2half2_rn(b.x, b.y);
    h[3] = __floats2half2_rn(b.z, b.w);
    ((uint4*)dst)[i] = *(uint4*)h;
}

// ---------------- per-row gate scalars ----------------
__global__ void row_scalars(const float* __restrict__ X, int M,
                            const float* __restrict__ wA, const float* __restrict__ wB,
                            float* __restrict__ outA, float* __restrict__ outB)
{
    int warp = (blockIdx.x * blockDim.x + threadIdx.x) >> 5;
    int lane = threadIdx.x & 31;
    if (warp >= M) return;
    const float4* xr = (const float4*)(X + (size_t)warp * DD);
    const float4* wa4 = (const float4*)wA;
    const float4* wb4 = (const float4*)wB;
    float sA = 0.f, sB = 0.f;
#pragma unroll
    for (int h = 0; h < 2; ++h) {
        int c4 = lane + h * 32;
        float4 v = xr[c4];
        float4 a = wa4[c4];
        float4 b = wb4[c4];
        float rx = fmaxf(v.x, 0.f), ry = fmaxf(v.y, 0.f);
        float rz = fmaxf(v.z, 0.f), rw = fmaxf(v.w, 0.f);
        sA += rx * a.x + ry * a.y + rz * a.z + rw * a.w;
        sB += rx * b.x + ry * b.y + rz * b.z + rw * b.w;
    }
#pragma unroll
    for (int o = 16; o > 0; o >>= 1) {
        sA += __shfl_xor_sync(0xFFFFFFFFu, sA, o);
        sB += __shfl_xor_sync(0xFFFFFFFFu, sB, o);
    }
    if (lane == 0) { outA[warp] = sA; outB[warp] = sB; }
}

// ---------------- zero msgO ----------------
__global__ void zero_kernel(float4* __restrict__ p, int n4)
{
    int i = blockIdx.x * blockDim.x + threadIdx.x;
    if (i < n4) p[i] = make_float4(0.f, 0.f, 0.f, 0.f);
}

// ---------------- edge kernel (msgP written directly as half) ----------------
__global__ void edge_kernel(const float* __restrict__ xp,
                            const float* __restrict__ xo,
                            const int*   __restrict__ pidx,
                            const float* __restrict__ aO1, const float* __restrict__ aO2,
                            const float* __restrict__ pP1, const float* __restrict__ pP2,
                            const float* __restrict__ b_e2v, const float* __restrict__ b_v2e,
                            float* __restrict__ msgO, __half* __restrict__ msgP)
{
    int e = (blockIdx.x * blockDim.x + threadIdx.x) >> 5;
    int lane = threadIdx.x & 31;
    if (e >= N_PAIR) return;

    int s = pidx[2 * e];
    int o = pidx[2 * e + 1];
    float be = b_e2v[0];
    float bv = b_v2e[0];
    float p1 = pP1[e], p2 = pP2[e];
    float g1 = sigf(aO1[s] + p1 + be);
    float g2 = sigf(aO1[o] + p1 + be);
    float gs = sigf(aO2[s] + p2 + bv);
    float go = sigf(aO2[o] + p2 + bv);

    const float4* xpr = (const float4*)(xp + (size_t)e * DD);
    const float4* xsr = (const float4*)(xo + (size_t)s * DD);
    const float4* xor4 = (const float4*)(xo + (size_t)o * DD);
    __half2* mp = (__half2*)(msgP + (size_t)e * DD);
    float4* mos = (float4*)(msgO + (size_t)s * DD);
    float4* moo = (float4*)(msgO + (size_t)o * DD);

#pragma unroll
    for (int h = 0; h < 2; ++h) {
        int c = lane + h * 32;
        float4 vp = xpr[c];
        float4 vs = xsr[c];
        float4 vo = xor4[c];

        float ox = gs * vs.x + go * vo.x;
        float oy = gs * vs.y + go * vo.y;
        float oz = gs * vs.z + go * vo.z;
        float ow = gs * vs.w + go * vo.w;
        mp[2 * c]     = __floats2half2_rn(ox, oy);
        mp[2 * c + 1] = __floats2half2_rn(oz, ow);

        float4 as = make_float4(g1 * vp.x, g1 * vp.y, g1 * vp.z, g1 * vp.w);
        float4 ao = make_float4(g2 * vp.x, g2 * vp.y, g2 * vp.z, g2 * vp.w);
        atomicAdd(&mos[c], as);
        atomicAdd(&moo[c], ao);
    }
}

// ================= fp16 mma.sync fused GRU =================
// Y = GRU(X, H), operands pre-converted to half in gmem. 4 accumulator groups:
//   accR = X@Wr_ih^T + H@Wr_hh^T ; accZ likewise ; accI = X@Wn_ih^T ; accN = H@Wn_hh^T
// BM=128, BN=32, BK=32 halves; 256 threads (8 warps: 4m x 2n, warp tile 32x16).
// mma.sync.m16n8k16 f16 -> f32 accum; epilogue reads FLOAT H for precision.
#define TBM 128
#define TBN 32
#define TBK 32            // halves per stage
#define ROWB 80           // smem row stride bytes (40 halves): conflict-free phases

#define ABUF (TBM * ROWB)            // 10240 B per matrix per buffer
#define BGT  (TBN * ROWB)            // 2560 B per gate tile
#define BBUF (6 * BGT)               // 15360 B per buffer
#define OFF_AX 0
#define OFF_AH (2 * ABUF)            // 20480
#define OFF_B  (4 * ABUF)            // 40960
#define GRU_SMEM (OFF_B + 2 * BBUF)  // 71680

__device__ __forceinline__ uint32_t smem_u32(const void* p) {
    return (uint32_t)__cvta_generic_to_shared(p);
}
#define CP16(dst, src) \
    asm volatile("cp.async.cg.shared.global [%0], [%1], 16;\n" :: "r"(dst), "l"(src) : "memory")
__device__ __forceinline__ void cp_commit() {
    asm volatile("cp.async.commit_group;\n" ::: "memory");
}
template<int N> __device__ __forceinline__ void cp_wait() {
    asm volatile("cp.async.wait_group %0;\n" :: "n"(N) : "memory");
}
__device__ __forceinline__ void ldsm4(uint32_t* r, uint32_t addr) {
    asm volatile("ldmatrix.sync.aligned.m8n8.x4.shared.b16 {%0,%1,%2,%3}, [%4];\n"
        : "=r"(r[0]), "=r"(r[1]), "=r"(r[2]), "=r"(r[3]) : "r"(addr));
}
__device__ __forceinline__ void mma_f16(float* c, const uint32_t* a, const uint32_t* b) {
    asm volatile("mma.sync.aligned.m16n8k16.row.col.f32.f16.f16.f32 "
        "{%0,%1,%2,%3}, {%4,%5,%6,%7}, {%8,%9}, {%0,%1,%2,%3};\n"
        : "+f"(c[0]), "+f"(c[1]), "+f"(c[2]), "+f"(c[3])
        : "r"(a[0]), "r"(a[1]), "r"(a[2]), "r"(a[3]), "r"(b[0]), "r"(b[1]));
}

__global__ __launch_bounds__(256, 2)
void gru_fp16(const __half* __restrict__ Xh, const __half* __restrict__ Hh,
              const float*  __restrict__ Hf,
              const __half* __restrict__ Wih, const __half* __restrict__ Whh,
              const float* __restrict__ bih, const float* __restrict__ bhh,
              float* __restrict__ Y)
{
    extern __shared__ __align__(128) char smem[];
    const uint32_t sb = smem_u32(smem);

    const int tid  = threadIdx.x;
    const int lane = tid & 31;
    const int w    = tid >> 5;
    const int wm   = w >> 1;     // 0..3
    const int wn   = w & 1;      // 0..1
    const int m0   = blockIdx.y * TBM;
    const int d0   = blockIdx.x * TBN;

    float acc[4][2][2][4] = {};  // [gate][mi][ni][reg]

    const int NSTAGE = DD / TBK;  // 8

    // ---- staging: global (half) -> smem via cp.async ----
    auto stage = [&](int kc, int buf) {
        const int k0 = kc * TBK;
#pragma unroll
        for (int j = 0; j < 2; ++j) {
            int slot = tid + 256 * j;       // 0..511
            int row = slot >> 2;            // 0..127
            int c   = slot & 3;             // 16B chunk (8 halves)
            uint32_t dx = sb + OFF_AX + buf * ABUF + row * ROWB + c * 16;
            CP16(dx, Xh + (size_t)(m0 + row) * DD + k0 + c * 8);
            uint32_t dh = sb + OFF_AH + buf * ABUF + row * ROWB + c * 16;
            CP16(dh, Hh + (size_t)(m0 + row) * DD + k0 + c * 8);
        }
#pragma unroll
        for (int j = 0; j < 3; ++j) {
            int slot = tid + 256 * j;       // 0..767
            int g = slot >> 7;              // 0..5
            int r = (slot >> 2) & 31;
            int c = slot & 3;
            const __half* W = (g < 3) ? Wih : Whh;
            int grow = (g % 3) * DD + d0 + r;
            uint32_t db = sb + OFF_B + buf * BBUF + g * BGT + r * ROWB + c * 16;
            CP16(db, W + (size_t)grow * DD + k0 + c * 8);
        }
    };

    stage(0, 0);
    cp_commit();

    // ldmatrix per-lane address components
    const int rowA  = lane & 15;
    const int colAh = (lane >> 4) * 16;                 // byte offset within k16 chunk
    const int rowB  = (lane & 7) + ((lane >> 4) * 8);   // n row
    const int colBh = ((lane >> 3) & 1) * 16;

#pragma unroll 1
    for (int kc = 0; kc < NSTAGE; ++kc) {
        const int buf = kc & 1;
        if (kc + 1 < NSTAGE) {
            stage(kc + 1, buf ^ 1);
            cp_commit();
            cp_wait<1>();
        } else {
            cp_wait<0>();
        }
        __syncthreads();

        const uint32_t aXb = sb + OFF_AX + buf * ABUF;
        const uint32_t aHb = sb + OFF_AH + buf * ABUF;
        const uint32_t bb  = sb + OFF_B  + buf * BBUF;

#pragma unroll
        for (int c = 0; c < 2; ++c) {       // two k16 chunks per stage
            uint32_t aX[2][4], aH[2][4], bf[6][4];
#pragma unroll
            for (int mi = 0; mi < 2; ++mi) {
                uint32_t ra = (wm * 32 + mi * 16 + rowA) * ROWB + c * 32 + colAh;
                ldsm4(aX[mi], aXb + ra);
                ldsm4(aH[mi], aHb + ra);
            }
#pragma unroll
            for (int g = 0; g < 6; ++g) {
                uint32_t rb = g * BGT + (wn * 16 + rowB) * ROWB + c * 32 + colBh;
                ldsm4(bf[g], bb + rb);
            }
            // bf[g] regs: {r0,r1} = n8 tile 0 (k-low,k-high), {r2,r3} = n8 tile 1
#pragma unroll
            for (int mi = 0; mi < 2; ++mi)
#pragma unroll
            for (int ni = 0; ni < 2; ++ni) {
                mma_f16(acc[0][mi][ni], aX[mi], &bf[0][2 * ni]);  // r: X@Wr_ih
                mma_f16(acc[0][mi][ni], aH[mi], &bf[3][2 * ni]);  // r: H@Wr_hh
                mma_f16(acc[1][mi][ni], aX[mi], &bf[1][2 * ni]);  // z: X@Wz_ih
                mma_f16(acc[1][mi][ni], aH[mi], &bf[4][2 * ni]);  // z: H@Wz_hh
                mma_f16(acc[2][mi][ni], aX[mi], &bf[2][2 * ni]);  // i_n
                mma_f16(acc[3][mi][ni], aH[mi], &bf[5][2 * ni]);  // h_n
            }
        }
        __syncthreads();
    }

    // ---- fused GRU epilogue (float H read, precise activations) ----
    const int mwarp = m0 + wm * 32;
    const int dwarp = d0 + wn * 16;
#pragma unroll
    for (int ni = 0; ni < 2; ++ni) {
        const int dA = dwarp + ni * 8 + (lane & 3) * 2;
        const float brA = __ldg(bih + dA)          + __ldg(bhh + dA);
        const float brB = __ldg(bih + dA + 1)      + __ldg(bhh + dA + 1);
        const float bzA = __ldg(bih + DD + dA)     + __ldg(bhh + DD + dA);
        const float bzB = __ldg(bih + DD + dA + 1) + __ldg(bhh + DD + dA + 1);
        const float biA = __ldg(bih + 2 * DD + dA);
        const float biB = __ldg(bih + 2 * DD + dA + 1);
        const float bnA = __ldg(bhh + 2 * DD + dA);
        const float bnB = __ldg(bhh + 2 * DD + dA + 1);
#pragma unroll
        for (int mi = 0; mi < 2; ++mi) {
#pragma unroll
            for (int p = 0; p < 2; ++p) {
                const int m = mwarp + mi * 16 + (lane >> 2) + p * 8;
                const float cr0 = acc[0][mi][ni][2 * p], cr1 = acc[0][mi][ni][2 * p + 1];
                const float cz0 = acc[1][mi][ni][2 * p], cz1 = acc[1][mi][ni][2 * p + 1];
                const float ci0 = acc[2][mi][ni][2 * p], ci1 = acc[2][mi][ni][2 * p + 1];
                const float cn0 = acc[3][mi][ni][2 * p], cn1 = acc[3][mi][ni][2 * p + 1];
                const float2 h2 = *(const float2*)(Hf + (size_t)m * DD + dA);
                const float r0 = sigf(cr0 + brA);
                const float r1 = sigf(cr1 + brB);
                const float z0 = sigf(cz0 + bzA);
                const float z1 = sigf(cz1 + bzB);
                const float n0 = tanhf(ci0 + biA + r0 * (cn0 + bnA));
                const float n1 = tanhf(ci1 + biB + r1 * (cn1 + bnB));
                float2 y2;
                y2.x = (1.0f - z0) * n0 + z0 * h2.x;
                y2.y = (1.0f - z1) * n1 + z1 * h2.y;
                *(float2*)(Y + (size_t)m * DD + dA) = y2;
            }
        }
    }
}

// ---------------- driver ----------------
static void run_step(const float* cur_obj, const float* cur_pred,
                     float* next_obj, float* next_pred,
                     const int* pidx,
                     const float* w_e2v, const float* b_e2v,
                     const float* w_v2e, const float* b_v2e,
                     const float* b_ih, const float* b_hh,
                     float* aO1, float* aO2, float* pP1, float* pP2,
                     float* msgO,
                     __half* msgO_h, __half* msgP_h, __half* objH_h, __half* predH_h,
                     const __half* Wih_h, const __half* Whh_h)
{
    row_scalars<<<(N_OBJ * 32 + 255) / 256, 256>>>(cur_obj, N_OBJ, w_e2v, w_v2e + DD, aO1, aO2);
    row_scalars<<<(N_PAIR * 32 + 255) / 256, 256>>>(cur_pred, N_PAIR, w_e2v + DD, w_v2e, pP1, pP2);
    zero_kernel<<<(N_OBJ * DD / 4 + 255) / 256, 256>>>((float4*)msgO, N_OBJ * DD / 4);
    // H half conversions (independent of edge kernel)
    f2h_kernel<<<(N_OBJ * DD / 8 + 255) / 256, 256>>>(cur_obj, objH_h, N_OBJ * DD / 8);
    f2h_kernel<<<(N_PAIR * DD / 8 + 255) / 256, 256>>>(cur_pred, predH_h, N_PAIR * DD / 8);
    // gates + scatter (msgO float atomics) + msgP half
    edge_kernel<<<(N_PAIR * 32 + 255) / 256, 256>>>(cur_pred, cur_obj, pidx,
                                                    aO1, aO2, pP1, pP2,
                                                    b_e2v, b_v2e, msgO, msgP_h);
    f2h_kernel<<<(N_OBJ * DD / 8 + 255) / 256, 256>>>(msgO, msgO_h, N_OBJ * DD / 8);
    // GRU updates (fp16 tensor cores)
    gru_fp16<<<dim3(DD / TBN, N_OBJ / TBM), 256, GRU_SMEM>>>(
        msgO_h, objH_h, cur_obj, Wih_h, Whh_h, b_ih, b_hh, next_obj);
    gru_fp16<<<dim3(DD / TBN, N_PAIR / TBM), 256, GRU_SMEM>>>(
        msgP_h, predH_h, cur_pred, Wih_h, Whh_h, b_ih, b_hh, next_pred);
}

extern "C" void kernel_launch(void* const* d_in, const int* in_sizes, int n_in,
                              void* d_out, int out_size)
{
    (void)in_sizes; (void)n_in; (void)out_size;
    const float* x_obj  = (const float*)d_in[0];
    const float* x_pred = (const float*)d_in[1];
    const int*   pidx   = (const int*)d_in[2];
    const float* w_e2v  = (const float*)d_in[3];
    const float* b_e2v  = (const float*)d_in[4];
    const float* w_v2e  = (const float*)d_in[5];
    const float* b_v2e  = (const float*)d_in[6];
    const float* w_ih   = (const float*)d_in[7];
    const float* w_hh   = (const float*)d_in[8];
    const float* b_ih   = (const float*)d_in[9];
    const float* b_hh   = (const float*)d_in[10];
    float* out = (float*)d_out;

    cudaFuncSetAttribute(gru_fp16, cudaFuncAttributeMaxDynamicSharedMemorySize, GRU_SMEM);

    float *objA, *predA, *msgO, *aO1, *aO2, *pP1, *pP2;
    __half *msgP_h, *msgO_h, *objH_h, *predH_h, *Wih_h, *Whh_h;
    cudaGetSymbolAddress((void**)&objA,   g_objA);
    cudaGetSymbolAddress((void**)&predA,  g_predA);
    cudaGetSymbolAddress((void**)&msgO,   g_msgO);
    cudaGetSymbolAddress((void**)&aO1,    g_aO1);
    cudaGetSymbolAddress((void**)&aO2,    g_aO2);
    cudaGetSymbolAddress((void**)&pP1,    g_pP1);
    cudaGetSymbolAddress((void**)&pP2,    g_pP2);
    cudaGetSymbolAddress((void**)&msgP_h, g_msgP_h);
    cudaGetSymbolAddress((void**)&msgO_h, g_msgO_h);
    cudaGetSymbolAddress((void**)&objH_h, g_objH_h);
    cudaGetSymbolAddress((void**)&predH_h,g_predH_h);
    cudaGetSymbolAddress((void**)&Wih_h,  g_Wih_h);
    cudaGetSymbolAddress((void**)&Whh_h,  g_Whh_h);

    // one-time weight conversion (deterministic every call)
    f2h_kernel<<<(3 * DD * DD / 8 + 255) / 256, 256>>>(w_ih, Wih_h, 3 * DD * DD / 8);
    f2h_kernel<<<(3 * DD * DD / 8 + 255) / 256, 256>>>(w_hh, Whh_h, 3 * DD * DD / 8);

    float* out_obj  = out;
    float* out_pred = out + (size_t)N_OBJ * DD;

    run_step(x_obj, x_pred, objA, predA, pidx,
             w_e2v, b_e2v, w_v2e, b_v2e, b_ih, b_hh,
             aO1, aO2, pP1, pP2, msgO,
             msgO_h, msgP_h, objH_h, predH_h, Wih_h, Whh_h);
    run_step(objA, predA, out_obj, out_pred, pidx,
             w_e2v, b_e2v, w_v2e, b_v2e, b_ih, b_hh,
             aO1, aO2, pP1, pP2, msgO,
             msgO_h, msgP_h, objH_h, predH_h, Wih_h, Whh_h);
}

// round 12
// speedup vs baseline: 4.8529x; 1.0752x over previous
#include <cuda_runtime.h>
#include <cuda_fp16.h>
#include <math.h>
#include <stdint.h>

#define N_OBJ  16384
#define N_PAIR 131072
#define DD     256

// ---------------- scratch (static device memory; no allocations) ----------------
__device__ float g_objA[(size_t)N_OBJ  * DD];
__device__ float g_predA[(size_t)N_PAIR * DD];
__device__ float g_msgO[(size_t)N_OBJ  * DD];
__device__ float g_aO1[N_OBJ];
__device__ float g_aO2[N_OBJ];
__device__ float g_pP1[N_PAIR];
__device__ float g_pP2[N_PAIR];
// half-precision MMA operand buffers
__device__ __half g_msgP_h[(size_t)N_PAIR * DD];
__device__ __half g_msgO_h[(size_t)N_OBJ  * DD];
__device__ __half g_objH_h[(size_t)N_OBJ  * DD];
__device__ __half g_predH_h[(size_t)N_PAIR * DD];
__device__ __half g_Wih_h[3 * DD * DD];
__device__ __half g_Whh_h[3 * DD * DD];

__device__ __forceinline__ float sigf(float x) { return 1.0f / (1.0f + expf(-x)); }

// ---------------- float -> half conversion (8 elems / thread) ----------------
__global__ void f2h_kernel(const float* __restrict__ src, __half* __restrict__ dst, int n8)
{
    int i = blockIdx.x * blockDim.x + threadIdx.x;
    if (i >= n8) return;
    const float4* s4 = (const float4*)src;
    float4 a = s4[2 * i];
    float4 b = s4[2 * i + 1];
    __half2 h[4];
    h[0] = __floats2half2_rn(a.x, a.y);
    h[1] = __floats2half2_rn(a.z, a.w);
    h[2] = __floats2half2_rn(b.x, b.y);
    h[3] = __floats2half2_rn(b.z, b.w);
    ((uint4*)dst)[i] = *(uint4*)h;
}

// ---------------- fused per-row gate scalars + half conversion ----------------
// One warp per row: computes dot(relu(row), wA), dot(relu(row), wB) AND writes
// the half-precision copy of the row (single read pass over X).
__global__ void rs_f2h_kernel(const float* __restrict__ X, int M,
                              const float* __restrict__ wA, const float* __restrict__ wB,
                              float* __restrict__ outA, float* __restrict__ outB,
                              __half* __restrict__ Xh)
{
    int row = (blockIdx.x * blockDim.x + threadIdx.x) >> 5;
    int lane = threadIdx.x & 31;
    if (row >= M) return;
    const float4* xr = (const float4*)(X + (size_t)row * DD);
    const float4* wa4 = (const float4*)wA;
    const float4* wb4 = (const float4*)wB;
    float sA = 0.f, sB = 0.f;
    __half2 hout[4];
#pragma unroll
    for (int h = 0; h < 2; ++h) {
        int c4 = 2 * lane + h;               // contiguous 8 floats per lane
        float4 v = xr[c4];
        float4 a = wa4[c4];
        float4 b = wb4[c4];
        float rx = fmaxf(v.x, 0.f), ry = fmaxf(v.y, 0.f);
        float rz = fmaxf(v.z, 0.f), rw = fmaxf(v.w, 0.f);
        sA += rx * a.x + ry * a.y + rz * a.z + rw * a.w;
        sB += rx * b.x + ry * b.y + rz * b.z + rw * b.w;
        hout[2 * h]     = __floats2half2_rn(v.x, v.y);
        hout[2 * h + 1] = __floats2half2_rn(v.z, v.w);
    }
    ((uint4*)(Xh + (size_t)row * DD))[lane] = *(uint4*)hout;
#pragma unroll
    for (int o = 16; o > 0; o >>= 1) {
        sA += __shfl_xor_sync(0xFFFFFFFFu, sA, o);
        sB += __shfl_xor_sync(0xFFFFFFFFu, sB, o);
    }
    if (lane == 0) { outA[row] = sA; outB[row] = sB; }
}

// ---------------- zero msgO ----------------
__global__ void zero_kernel(float4* __restrict__ p, int n4)
{
    int i = blockIdx.x * blockDim.x + threadIdx.x;
    if (i < n4) p[i] = make_float4(0.f, 0.f, 0.f, 0.f);
}

// ---------------- edge kernel (msgP written directly as half) ----------------
__global__ void edge_kernel(const float* __restrict__ xp,
                            const float* __restrict__ xo,
                            const int*   __restrict__ pidx,
                            const float* __restrict__ aO1, const float* __restrict__ aO2,
                            const float* __restrict__ pP1, const float* __restrict__ pP2,
                            const float* __restrict__ b_e2v, const float* __restrict__ b_v2e,
                            float* __restrict__ msgO, __half* __restrict__ msgP)
{
    int e = (blockIdx.x * blockDim.x + threadIdx.x) >> 5;
    int lane = threadIdx.x & 31;
    if (e >= N_PAIR) return;

    int s = pidx[2 * e];
    int o = pidx[2 * e + 1];
    float be = b_e2v[0];
    float bv = b_v2e[0];
    float p1 = pP1[e], p2 = pP2[e];
    float g1 = sigf(aO1[s] + p1 + be);
    float g2 = sigf(aO1[o] + p1 + be);
    float gs = sigf(aO2[s] + p2 + bv);
    float go = sigf(aO2[o] + p2 + bv);

    const float4* xpr = (const float4*)(xp + (size_t)e * DD);
    const float4* xsr = (const float4*)(xo + (size_t)s * DD);
    const float4* xor4 = (const float4*)(xo + (size_t)o * DD);
    __half2* mp = (__half2*)(msgP + (size_t)e * DD);
    float4* mos = (float4*)(msgO + (size_t)s * DD);
    float4* moo = (float4*)(msgO + (size_t)o * DD);

#pragma unroll
    for (int h = 0; h < 2; ++h) {
        int c = lane + h * 32;
        float4 vp = xpr[c];
        float4 vs = xsr[c];
        float4 vo = xor4[c];

        float ox = gs * vs.x + go * vo.x;
        float oy = gs * vs.y + go * vo.y;
        float oz = gs * vs.z + go * vo.z;
        float ow = gs * vs.w + go * vo.w;
        mp[2 * c]     = __floats2half2_rn(ox, oy);
        mp[2 * c + 1] = __floats2half2_rn(oz, ow);

        float4 as = make_float4(g1 * vp.x, g1 * vp.y, g1 * vp.z, g1 * vp.w);
        float4 ao = make_float4(g2 * vp.x, g2 * vp.y, g2 * vp.z, g2 * vp.w);
        atomicAdd(&mos[c], as);
        atomicAdd(&moo[c], ao);
    }
}

// ================= fp16 mma.sync fused GRU =================
// Y = GRU(X, H). 4 accumulator groups:
//   accR = X@Wr_ih^T + H@Wr_hh^T ; accZ likewise ; accI = X@Wn_ih^T ; accN = H@Wn_hh^T
// BM=128, BN=32, BK=32 halves; 256 threads (8 warps: 4m x 2n, warp tile 32x16).
// 3-stage cp.async ring. H for the output blend is captured from the AsH
// staging tile at stage kc == blockIdx.x (K-range == D-range), so the epilogue
// does no gmem H read.
#define TBM 128
#define TBN 32
#define TBK 32            // halves per stage
#define ROWB 80           // smem row stride bytes (40 halves)
#define NBUF 3

#define ABUF (TBM * ROWB)            // 10240 B per matrix per buffer
#define BGT  (TBN * ROWB)            // 2560 B per gate tile
#define BBUF (6 * BGT)               // 15360 B per buffer
#define OFF_AX 0
#define OFF_AH (NBUF * ABUF)         // 30720
#define OFF_B  (2 * NBUF * ABUF)     // 61440
#define GRU_SMEM (OFF_B + NBUF * BBUF)  // 107520

__device__ __forceinline__ uint32_t smem_u32(const void* p) {
    return (uint32_t)__cvta_generic_to_shared(p);
}
#define CP16(dst, src) \
    asm volatile("cp.async.cg.shared.global [%0], [%1], 16;\n" :: "r"(dst), "l"(src) : "memory")
__device__ __forceinline__ void cp_commit() {
    asm volatile("cp.async.commit_group;\n" ::: "memory");
}
template<int N> __device__ __forceinline__ void cp_wait() {
    asm volatile("cp.async.wait_group %0;\n" :: "n"(N) : "memory");
}
__device__ __forceinline__ void ldsm4(uint32_t* r, uint32_t addr) {
    asm volatile("ldmatrix.sync.aligned.m8n8.x4.shared.b16 {%0,%1,%2,%3}, [%4];\n"
        : "=r"(r[0]), "=r"(r[1]), "=r"(r[2]), "=r"(r[3]) : "r"(addr));
}
__device__ __forceinline__ void mma_f16(float* c, const uint32_t* a, const uint32_t* b) {
    asm volatile("mma.sync.aligned.m16n8k16.row.col.f32.f16.f16.f32 "
        "{%0,%1,%2,%3}, {%4,%5,%6,%7}, {%8,%9}, {%0,%1,%2,%3};\n"
        : "+f"(c[0]), "+f"(c[1]), "+f"(c[2]), "+f"(c[3])
        : "r"(a[0]), "r"(a[1]), "r"(a[2]), "r"(a[3]), "r"(b[0]), "r"(b[1]));
}

__global__ __launch_bounds__(256, 2)
void gru_fp16(const __half* __restrict__ Xh, const __half* __restrict__ Hh,
              const __half* __restrict__ Wih, const __half* __restrict__ Whh,
              const float* __restrict__ bih, const float* __restrict__ bhh,
              float* __restrict__ Y)
{
    extern __shared__ __align__(128) char smem[];
    const uint32_t sb = smem_u32(smem);

    const int tid  = threadIdx.x;
    const int lane = tid & 31;
    const int w    = tid >> 5;
    const int wm   = w >> 1;     // 0..3
    const int wn   = w & 1;      // 0..1
    const int m0   = blockIdx.y * TBM;
    const int d0   = blockIdx.x * TBN;
    const int bn   = blockIdx.x;  // d-block == k-stage index holding our H cols

    float acc[4][2][2][4] = {};  // [gate][mi][ni][reg]
    float2 hval[2][2][2];        // [ni][mi][p] blend H, captured from smem

    const int NSTAGE = DD / TBK;  // 8

    // ---- staging: global (half) -> smem via cp.async ----
    auto stage = [&](int kc, int buf) {
        const int k0 = kc * TBK;
#pragma unroll
        for (int j = 0; j < 2; ++j) {
            int slot = tid + 256 * j;       // 0..511
            int row = slot >> 2;            // 0..127
            int c   = slot & 3;             // 16B chunk (8 halves)
            uint32_t dx = sb + OFF_AX + buf * ABUF + row * ROWB + c * 16;
            CP16(dx, Xh + (size_t)(m0 + row) * DD + k0 + c * 8);
            uint32_t dh = sb + OFF_AH + buf * ABUF + row * ROWB + c * 16;
            CP16(dh, Hh + (size_t)(m0 + row) * DD + k0 + c * 8);
        }
#pragma unroll
        for (int j = 0; j < 3; ++j) {
            int slot = tid + 256 * j;       // 0..767
            int g = slot >> 7;              // 0..5
            int r = (slot >> 2) & 31;
            int c = slot & 3;
            const __half* W = (g < 3) ? Wih : Whh;
            int grow = (g % 3) * DD + d0 + r;
            uint32_t db = sb + OFF_B + buf * BBUF + g * BGT + r * ROWB + c * 16;
            CP16(db, W + (size_t)grow * DD + k0 + c * 8);
        }
    };

    stage(0, 0); cp_commit();
    stage(1, 1); cp_commit();

    // ldmatrix per-lane address components
    const int rowA  = lane & 15;
    const int colAh = (lane >> 4) * 16;
    const int rowB  = (lane & 7) + ((lane >> 4) * 8);
    const int colBh = ((lane >> 3) & 1) * 16;

#pragma unroll 1
    for (int kc = 0; kc < NSTAGE; ++kc) {
        int buf = kc % NBUF;
        if (kc + 2 < NSTAGE) {
            stage(kc + 2, (kc + 2) % NBUF);
            cp_commit();
            cp_wait<2>();
        } else if (kc + 1 < NSTAGE) {
            cp_wait<1>();
        } else {
            cp_wait<0>();
        }
        __syncthreads();

        if (kc == bn) {
            // H columns for this block's outputs live in this AsH tile
            const char* hb = smem + OFF_AH + buf * ABUF;
#pragma unroll
            for (int ni = 0; ni < 2; ++ni)
#pragma unroll
            for (int mi = 0; mi < 2; ++mi)
#pragma unroll
            for (int p = 0; p < 2; ++p) {
                int mr = wm * 32 + mi * 16 + (lane >> 2) + p * 8;
                int cc = wn * 16 + ni * 8 + (lane & 3) * 2;
                __half2 hh = *(const __half2*)(hb + mr * ROWB + cc * 2);
                hval[ni][mi][p] = __half22float2(hh);
            }
        }

        const uint32_t aXb = sb + OFF_AX + buf * ABUF;
        const uint32_t aHb = sb + OFF_AH + buf * ABUF;
        const uint32_t bb  = sb + OFF_B  + buf * BBUF;

#pragma unroll
        for (int c = 0; c < 2; ++c) {       // two k16 chunks per stage
            uint32_t aX[2][4], aH[2][4], bf[6][4];
#pragma unroll
            for (int mi = 0; mi < 2; ++mi) {
                uint32_t ra = (wm * 32 + mi * 16 + rowA) * ROWB + c * 32 + colAh;
                ldsm4(aX[mi], aXb + ra);
                ldsm4(aH[mi], aHb + ra);
            }
#pragma unroll
            for (int g = 0; g < 6; ++g) {
                uint32_t rb = g * BGT + (wn * 16 + rowB) * ROWB + c * 32 + colBh;
                ldsm4(bf[g], bb + rb);
            }
#pragma unroll
            for (int mi = 0; mi < 2; ++mi)
#pragma unroll
            for (int ni = 0; ni < 2; ++ni) {
                mma_f16(acc[0][mi][ni], aX[mi], &bf[0][2 * ni]);  // r: X@Wr_ih
                mma_f16(acc[0][mi][ni], aH[mi], &bf[3][2 * ni]);  // r: H@Wr_hh
                mma_f16(acc[1][mi][ni], aX[mi], &bf[1][2 * ni]);  // z: X@Wz_ih
                mma_f16(acc[1][mi][ni], aH[mi], &bf[4][2 * ni]);  // z: H@Wz_hh
                mma_f16(acc[2][mi][ni], aX[mi], &bf[2][2 * ni]);  // i_n
                mma_f16(acc[3][mi][ni], aH[mi], &bf[5][2 * ni]);  // h_n
            }
        }
        __syncthreads();
    }

    // ---- fused GRU epilogue (H blend from registers) ----
    const int mwarp = m0 + wm * 32;
    const int dwarp = d0 + wn * 16;
#pragma unroll
    for (int ni = 0; ni < 2; ++ni) {
        const int dA = dwarp + ni * 8 + (lane & 3) * 2;
        const float brA = __ldg(bih + dA)          + __ldg(bhh + dA);
        const float brB = __ldg(bih + dA + 1)      + __ldg(bhh + dA + 1);
        const float bzA = __ldg(bih + DD + dA)     + __ldg(bhh + DD + dA);
        const float bzB = __ldg(bih + DD + dA + 1) + __ldg(bhh + DD + dA + 1);
        const float biA = __ldg(bih + 2 * DD + dA);
        const float biB = __ldg(bih + 2 * DD + dA + 1);
        const float bnA = __ldg(bhh + 2 * DD + dA);
        const float bnB = __ldg(bhh + 2 * DD + dA + 1);
#pragma unroll
        for (int mi = 0; mi < 2; ++mi) {
#pragma unroll
            for (int p = 0; p < 2; ++p) {
                const int m = mwarp + mi * 16 + (lane >> 2) + p * 8;
                const float cr0 = acc[0][mi][ni][2 * p], cr1 = acc[0][mi][ni][2 * p + 1];
                const float cz0 = acc[1][mi][ni][2 * p], cz1 = acc[1][mi][ni][2 * p + 1];
                const float ci0 = acc[2][mi][ni][2 * p], ci1 = acc[2][mi][ni][2 * p + 1];
                const float cn0 = acc[3][mi][ni][2 * p], cn1 = acc[3][mi][ni][2 * p + 1];
                const float2 h2 = hval[ni][mi][p];
                const float r0 = sigf(cr0 + brA);
                const float r1 = sigf(cr1 + brB);
                const float z0 = sigf(cz0 + bzA);
                const float z1 = sigf(cz1 + bzB);
                const float n0 = tanhf(ci0 + biA + r0 * (cn0 + bnA));
                const float n1 = tanhf(ci1 + biB + r1 * (cn1 + bnB));
                float2 y2;
                y2.x = (1.0f - z0) * n0 + z0 * h2.x;
                y2.y = (1.0f - z1) * n1 + z1 * h2.y;
                *(float2*)(Y + (size_t)m * DD + dA) = y2;
            }
        }
    }
}

// ---------------- driver ----------------
static void run_step(const float* cur_obj, const float* cur_pred,
                     float* next_obj, float* next_pred,
                     const int* pidx,
                     const float* w_e2v, const float* b_e2v,
                     const float* w_v2e, const float* b_v2e,
                     const float* b_ih, const float* b_hh,
                     float* aO1, float* aO2, float* pP1, float* pP2,
                     float* msgO,
                     __half* msgO_h, __half* msgP_h, __half* objH_h, __half* predH_h,
                     const __half* Wih_h, const __half* Whh_h)
{
    // fused: gate scalars + half conversion (single read pass)
    rs_f2h_kernel<<<(N_OBJ * 32 + 255) / 256, 256>>>(cur_obj, N_OBJ, w_e2v, w_v2e + DD,
                                                     aO1, aO2, objH_h);
    rs_f2h_kernel<<<(N_PAIR * 32 + 255) / 256, 256>>>(cur_pred, N_PAIR, w_e2v + DD, w_v2e,
                                                      pP1, pP2, predH_h);
    zero_kernel<<<(N_OBJ * DD / 4 + 255) / 256, 256>>>((float4*)msgO, N_OBJ * DD / 4);
    edge_kernel<<<(N_PAIR * 32 + 255) / 256, 256>>>(cur_pred, cur_obj, pidx,
                                                    aO1, aO2, pP1, pP2,
                                                    b_e2v, b_v2e, msgO, msgP_h);
    f2h_kernel<<<(N_OBJ * DD / 8 + 255) / 256, 256>>>(msgO, msgO_h, N_OBJ * DD / 8);
    gru_fp16<<<dim3(DD / TBN, N_OBJ / TBM), 256, GRU_SMEM>>>(
        msgO_h, objH_h, Wih_h, Whh_h, b_ih, b_hh, next_obj);
    gru_fp16<<<dim3(DD / TBN, N_PAIR / TBM), 256, GRU_SMEM>>>(
        msgP_h, predH_h, Wih_h, Whh_h, b_ih, b_hh, next_pred);
}

extern "C" void kernel_launch(void* const* d_in, const int* in_sizes, int n_in,
                              void* d_out, int out_size)
{
    (void)in_sizes; (void)n_in; (void)out_size;
    const float* x_obj  = (const float*)d_in[0];
    const float* x_pred = (const float*)d_in[1];
    const int*   pidx   = (const int*)d_in[2];
    const float* w_e2v  = (const float*)d_in[3];
    const float* b_e2v  = (const float*)d_in[4];
    const float* w_v2e  = (const float*)d_in[5];
    const float* b_v2e  = (const float*)d_in[6];
    const float* w_ih   = (const float*)d_in[7];
    const float* w_hh   = (const float*)d_in[8];
    const float* b_ih   = (const float*)d_in[9];
    const float* b_hh   = (const float*)d_in[10];
    float* out = (float*)d_out;

    cudaFuncSetAttribute(gru_fp16, cudaFuncAttributeMaxDynamicSharedMemorySize, GRU_SMEM);

    float *objA, *predA, *msgO, *aO1, *aO2, *pP1, *pP2;
    __half *msgP_h, *msgO_h, *objH_h, *predH_h, *Wih_h, *Whh_h;
    cudaGetSymbolAddress((void**)&objA,   g_objA);
    cudaGetSymbolAddress((void**)&predA,  g_predA);
    cudaGetSymbolAddress((void**)&msgO,   g_msgO);
    cudaGetSymbolAddress((void**)&aO1,    g_aO1);
    cudaGetSymbolAddress((void**)&aO2,    g_aO2);
    cudaGetSymbolAddress((void**)&pP1,    g_pP1);
    cudaGetSymbolAddress((void**)&pP2,    g_pP2);
    cudaGetSymbolAddress((void**)&msgP_h, g_msgP_h);
    cudaGetSymbolAddress((void**)&msgO_h, g_msgO_h);
    cudaGetSymbolAddress((void**)&objH_h, g_objH_h);
    cudaGetSymbolAddress((void**)&predH_h,g_predH_h);
    cudaGetSymbolAddress((void**)&Wih_h,  g_Wih_h);
    cudaGetSymbolAddress((void**)&Whh_h,  g_Whh_h);

    // weight conversion (deterministic every call)
    f2h_kernel<<<(3 * DD * DD / 8 + 255) / 256, 256>>>(w_ih, Wih_h, 3 * DD * DD / 8);
    f2h_kernel<<<(3 * DD * DD / 8 + 255) / 256, 256>>>(w_hh, Whh_h, 3 * DD * DD / 8);

    float* out_obj  = out;
    float* out_pred = out + (size_t)N_OBJ * DD;

    run_step(x_obj, x_pred, objA, predA, pidx,
             w_e2v, b_e2v, w_v2e, b_v2e, b_ih, b_hh,
             aO1, aO2, pP1, pP2, msgO,
             msgO_h, msgP_h, objH_h, predH_h, Wih_h, Whh_h);
    run_step(objA, predA, out_obj, out_pred, pidx,
             w_e2v, b_e2v, w_v2e, b_v2e, b_ih, b_hh,
             aO1, aO2, pP1, pP2, msgO,
             msgO_h, msgP_h, objH_h, predH_h, Wih_h, Whh_h);
}